// round 12
// baseline (speedup 1.0000x reference)
#include <cuda_runtime.h>
#include <cuda_fp16.h>
#include <cstdint>

#define DIM 128
#define OUTD 64
#define BC 64
#define SPLITS 18
#define THREADS 256
#define NPAD 50048              // 782 * 64, padded train rows
#define NFEAT 2048

#define TSTRIDE 136             // fp16 per row of A/T tiles
#define TROWB   (TSTRIDE * 2)   // 272 B
#define WROWB   144             // W tile row bytes (72 halfs)

#define OFF_A   0
#define SZ_A    (128 * TROWB)             // 34816
#define OFF_T   (OFF_A + SZ_A)
#define SZ_T    (BC * TROWB)              // 17408 x2
#define OFF_W   (OFF_T + 2 * SZ_T)        // 69632
#define SZ_W    (BC * WROWB)              // 9216  x2
#define OFF_T2  (OFF_W + 2 * SZ_W)        // 88064, 2 x 512B
#define SMEM_TOTAL (OFF_T2 + 1024)        // 89088  -> 2 CTAs/SM

// k = exp(-dist/(2*RBF)) = 2^(-sqrt(d2p)), d2p = B2C*(x2 + t2 - 2 dot)
#define B2C ((float)((1.4426950408889634 / (2.0 * 10.077141124806595)) * \
                     (1.4426950408889634 / (2.0 * 10.077141124806595))))
#define NEG2B2C (-2.0f * B2C)

// prep_all grid partition
#define ROWBLKS ((NPAD + NFEAT) / 8)
#define WBLKS   (NPAD * OUTD / 4 / THREADS)
#define ZBLKS   (NFEAT * OUTD / 4 / THREADS)
#define PREP_GRID (ROWBLKS + WBLKS + ZBLKS)

// ---- persistent device scratch ----
__device__ __half d_train16[NPAD * DIM];
__device__ __half d_w16[NPAD * OUTD];
__device__ __half d_feat16[NFEAT * DIM];
__device__ float  d_t2[NPAD];
__device__ float  d_x2[NFEAT];

// ---------- PTX helpers ----------
__device__ __forceinline__ uint32_t smem_u32(const void* p) {
    uint32_t a;
    asm("{ .reg .u64 t; cvta.to.shared.u64 t, %1; cvt.u32.u64 %0, t; }"
        : "=r"(a) : "l"(p));
    return a;
}
__device__ __forceinline__ void cpa16(uint32_t dst, const void* src) {
    asm volatile("cp.async.cg.shared.global [%0], [%1], 16;"
                 :: "r"(dst), "l"(src));
}
#define CP_COMMIT() asm volatile("cp.async.commit_group;" ::: "memory")
#define CP_WAIT0()  asm volatile("cp.async.wait_group 0;" ::: "memory")

__device__ __forceinline__ void ldsm4(uint32_t* r, uint32_t addr) {
    asm volatile("ldmatrix.sync.aligned.m8n8.x4.shared.b16 {%0,%1,%2,%3}, [%4];"
                 : "=r"(r[0]), "=r"(r[1]), "=r"(r[2]), "=r"(r[3]) : "r"(addr));
}
__device__ __forceinline__ void ldsm4t(uint32_t* r, uint32_t addr) {
    asm volatile("ldmatrix.sync.aligned.m8n8.x4.trans.shared.b16 {%0,%1,%2,%3}, [%4];"
                 : "=r"(r[0]), "=r"(r[1]), "=r"(r[2]), "=r"(r[3]) : "r"(addr));
}
__device__ __forceinline__ void mma_f16(float* c, const uint32_t* a, const uint32_t* b) {
    asm volatile("mma.sync.aligned.m16n8k16.row.col.f32.f16.f16.f32 "
                 "{%0,%1,%2,%3}, {%4,%5,%6,%7}, {%8,%9}, {%0,%1,%2,%3};"
                 : "+f"(c[0]), "+f"(c[1]), "+f"(c[2]), "+f"(c[3])
                 : "r"(a[0]), "r"(a[1]), "r"(a[2]), "r"(a[3]), "r"(b[0]), "r"(b[1]));
}
__device__ __forceinline__ float fast_sqrt(float x) {
    float r; asm("sqrt.approx.f32 %0, %1;" : "=f"(r) : "f"(x)); return r;
}
__device__ __forceinline__ float fast_ex2(float x) {
    float r; asm("ex2.approx.f32 %0, %1;" : "=f"(r) : "f"(x)); return r;
}
__device__ __forceinline__ uint32_t pack_h2(float a, float b) {
    __half2 p = __floats2half2_rn(a, b);
    return *(uint32_t*)&p;
}

// ---------- fused prep kernel ----------
__global__ void prep_all(const float* __restrict__ feat,
                         const float* __restrict__ train,
                         const float* __restrict__ w,
                         float* __restrict__ out, int N, int n) {
    int b = blockIdx.x;
    if (b < ROWBLKS) {
        int r = b * 8 + (threadIdx.x >> 5);
        int lid = threadIdx.x & 31;
        const float* src; __half* dst; float* nrm; int nValid, row;
        if (r < NPAD) { src = train; dst = d_train16; nrm = d_t2; nValid = N;  row = r; }
        else          { src = feat;  dst = d_feat16;  nrm = d_x2; nValid = n; row = r - NPAD; }
        float4 v = make_float4(0.f, 0.f, 0.f, 0.f);
        if (row < nValid) v = *(const float4*)(src + (size_t)row * DIM + lid * 4);
        uint32_t p0 = pack_h2(v.x, v.y), p1 = pack_h2(v.z, v.w);
        *(uint2*)(dst + (size_t)row * DIM + lid * 4) = make_uint2(p0, p1);
        float2 f0 = __half22float2(*(__half2*)&p0);
        float2 f1 = __half22float2(*(__half2*)&p1);
        float s = f0.x * f0.x + f0.y * f0.y + f1.x * f1.x + f1.y * f1.y;
        #pragma unroll
        for (int o = 16; o > 0; o >>= 1) s += __shfl_xor_sync(0xffffffffu, s, o);
        if (lid == 0) nrm[row] = s * B2C;
    } else if (b < ROWBLKS + WBLKS) {
        int idx = (b - ROWBLKS) * THREADS + threadIdx.x;
        int r = idx >> 4, c4 = idx & 15;
        float4 v = make_float4(0.f, 0.f, 0.f, 0.f);
        if (r < N) v = *(const float4*)(w + (size_t)r * OUTD + c4 * 4);
        *(uint2*)(d_w16 + (size_t)r * OUTD + c4 * 4) =
            make_uint2(pack_h2(v.x, v.y), pack_h2(v.z, v.w));
    } else {
        int idx = (b - ROWBLKS - WBLKS) * THREADS + threadIdx.x;
        ((float4*)out)[idx] = make_float4(0.f, 0.f, 0.f, 0.f);
    }
}

// ---------- main fused kernel ----------
__global__ void __launch_bounds__(THREADS, 2)
rbf_f16_kernel(float* __restrict__ out, int nChunks, int cps)
{
    extern __shared__ uint8_t sm[];
    uint32_t smb = smem_u32(sm);

    const int t = threadIdx.x, wid = t >> 5, lid = t & 31;
    const int qr = lid >> 2, qc = lid & 3;
    const int mb = wid >> 1;         // row band of 32: rows mb*32..
    const int kh = wid & 1;          // k-half: chunk cols kh*32..

    const int rowBase = blockIdx.x * 128;
    const int chunk0  = blockIdx.y * cps;
    const int nc      = min(chunk0 + cps, nChunks) - chunk0;

    const int tr = t >> 4, tc16 = t & 15;
    const int wr = t >> 3, wc8 = t & 7;

    // chunk-advanced source pointers (fold inner offsets into immediates)
    const __half* pT  = d_train16 + (size_t)(chunk0 * BC + tr) * DIM + tc16 * 8;
    const __half* pW  = d_w16     + (size_t)(chunk0 * BC + wr) * OUTD + wc8 * 8;
    const float*  pT2 = d_t2 + chunk0 * BC + t * 4;

    // ---- prologue: A + chunk0 tiles in one group ----
    #pragma unroll
    for (int i = 0; i < 8; i++)
        cpa16(smb + OFF_A + (uint32_t)(tr + i * 16) * TROWB + tc16 * 16,
              d_feat16 + (size_t)(rowBase + tr + i * 16) * DIM + tc16 * 8);
    #pragma unroll
    for (int i = 0; i < 4; i++)
        cpa16(smb + OFF_T + (uint32_t)(tr + i * 16) * TROWB + tc16 * 16,
              pT + (size_t)i * 16 * DIM);
    #pragma unroll
    for (int i = 0; i < 2; i++)
        cpa16(smb + OFF_W + (uint32_t)(wr + i * 32) * WROWB + wc8 * 16,
              pW + (size_t)i * 32 * OUTD);
    if (t < 16) cpa16(smb + OFF_T2 + t * 16, pT2);
    CP_COMMIT();

    // x2 (pre-scaled) for this warp's 32 rows
    float x2v[2][2];
    #pragma unroll
    for (int mi = 0; mi < 2; mi++) {
        x2v[mi][0] = d_x2[rowBase + mb * 32 + mi * 16 + qr];
        x2v[mi][1] = d_x2[rowBase + mb * 32 + mi * 16 + qr + 8];
    }

    const int aRowL    = lid & 15;
    const int aColHalf = (lid >> 4) << 3;
    const int bRowOff  = ((lid >> 4) << 3) + (lid & 7);
    const int bColOff  = lid & 8;
    const int wKrow    = (((lid >> 3) & 1) << 3) + (lid & 7);
    const int wNcol    = (lid >> 4) << 3;

    float c2[2][8][4];
    #pragma unroll
    for (int mi = 0; mi < 2; mi++)
        #pragma unroll
        for (int nt = 0; nt < 8; nt++)
            #pragma unroll
            for (int q = 0; q < 4; q++) c2[mi][nt][q] = 0.f;

    CP_WAIT0();
    __syncthreads();

    for (int i = 0; i < nc; i++) {
        const int cur = i & 1, nxt = cur ^ 1;
        const uint32_t sTb = smb + OFF_T + cur * SZ_T;
        const uint32_t sWb = smb + OFF_W + cur * SZ_W;
        const float* sT2c = (const float*)(sm + OFF_T2 + cur * 512);

        // ---- prefetch chunk i+1 into [nxt] ----
        if (i + 1 < nc) {
            pT  += BC * DIM;
            pW  += BC * OUTD;
            pT2 += BC;
            #pragma unroll
            for (int j = 0; j < 4; j++)
                cpa16(smb + OFF_T + nxt * SZ_T
                          + (uint32_t)(tr + j * 16) * TROWB + tc16 * 16,
                      pT + (size_t)j * 16 * DIM);
            #pragma unroll
            for (int j = 0; j < 2; j++)
                cpa16(smb + OFF_W + nxt * SZ_W
                          + (uint32_t)(wr + j * 32) * WROWB + wc8 * 16,
                      pW + (size_t)j * 32 * OUTD);
            if (t < 16) cpa16(smb + OFF_T2 + nxt * 512 + t * 16, pT2);
        }
        CP_COMMIT();

        // ---- GEMM1: c1 = A[mb*32.., :] @ T[kh*32.., :]^T  (32 x 32) ----
        float c1[2][4][4];
        #pragma unroll
        for (int mi = 0; mi < 2; mi++)
            #pragma unroll
            for (int nj = 0; nj < 4; nj++)
                #pragma unroll
                for (int q = 0; q < 4; q++) c1[mi][nj][q] = 0.f;

        #pragma unroll
        for (int ks = 0; ks < 8; ks++) {
            const int k0 = ks * 16;
            uint32_t a[2][4];
            #pragma unroll
            for (int mi = 0; mi < 2; mi++)
                ldsm4(a[mi], smb + OFF_A
                      + (uint32_t)(mb * 32 + mi * 16 + aRowL) * TROWB
                      + (uint32_t)(k0 + aColHalf) * 2);
            #pragma unroll
            for (int p = 0; p < 2; p++) {
                uint32_t rr[4];
                ldsm4(rr, sTb
                      + (uint32_t)(kh * 32 + p * 16 + bRowOff) * TROWB
                      + (uint32_t)(k0 + bColOff) * 2);
                #pragma unroll
                for (int mi = 0; mi < 2; mi++) {
                    mma_f16(c1[mi][2 * p],     a[mi], &rr[0]);
                    mma_f16(c1[mi][2 * p + 1], a[mi], &rr[2]);
                }
            }
        }

        // ---- per-16-col slice: epilogue -> A-frags -> GEMM2 ----
        #pragma unroll
        for (int s = 0; s < 2; s++) {
            const int cb = kh * 32 + s * 16;
            float2 t2a = *(float2*)&sT2c[cb + 2 * qc];
            float2 t2b = *(float2*)&sT2c[cb + 8 + 2 * qc];
            uint32_t ah[2][4];
            #pragma unroll
            for (int mi = 0; mi < 2; mi++) {
                float kk[2][4];
                #pragma unroll
                for (int half = 0; half < 2; half++) {
                    const float* cc = c1[mi][2 * s + half];
                    float2 t2p = half ? t2b : t2a;
                    #pragma unroll
                    for (int q = 0; q < 4; q++) {
                        float x2q = x2v[mi][q >> 1];
                        float tq  = (q & 1) ? t2p.y : t2p.x;
                        float d2  = fmaxf(fmaf(NEG2B2C, cc[q], x2q + tq), 0.f);
                        kk[half][q] = fast_ex2(-fast_sqrt(d2));
                    }
                }
                #pragma unroll
                for (int r = 0; r < 4; r++)
                    ah[mi][r] = pack_h2(kk[r >> 1][(r & 1) * 2],
                                        kk[r >> 1][(r & 1) * 2 + 1]);
            }

            const uint32_t wrow = (uint32_t)(cb + wKrow) * WROWB;
            #pragma unroll
            for (int u = 0; u < 4; u++) {
                uint32_t bh[4];
                ldsm4t(bh, sWb + wrow + (uint32_t)(u * 16 + wNcol) * 2);
                #pragma unroll
                for (int mi = 0; mi < 2; mi++) {
                    mma_f16(c2[mi][2 * u],     ah[mi], &bh[0]);
                    mma_f16(c2[mi][2 * u + 1], ah[mi], &bh[2]);
                }
            }
        }

        CP_WAIT0();
        __syncthreads();
    }

    // ---- accumulate into global out (kh halves + splits via atomics) ----
    #pragma unroll
    for (int mi = 0; mi < 2; mi++) {
        #pragma unroll
        for (int nt = 0; nt < 8; nt++) {
            int c = nt * 8 + 2 * qc;
            #pragma unroll
            for (int q = 0; q < 4; q++) {
                int r = rowBase + mb * 32 + mi * 16 + qr + ((q >> 1) << 3);
                atomicAdd(out + (size_t)r * OUTD + c + (q & 1), c2[mi][nt][q]);
            }
        }
    }
}

extern "C" void kernel_launch(void* const* d_in, const int* in_sizes, int n_in,
                              void* d_out, int out_size) {
    const float* features = (const float*)d_in[0];
    const float* train    = (const float*)d_in[1];
    const float* weights  = (const float*)d_in[2];
    float* out = (float*)d_out;

    int n = in_sizes[0] / DIM;    // 2048
    int N = in_sizes[1] / DIM;    // 50000

    int nChunks = (N + BC - 1) / BC;                 // 782
    int cps     = (nChunks + SPLITS - 1) / SPLITS;   // 44

    cudaFuncSetAttribute(rbf_f16_kernel,
                         cudaFuncAttributeMaxDynamicSharedMemorySize, SMEM_TOTAL);

    prep_all<<<PREP_GRID, THREADS>>>(features, train, weights, out, N, n);

    dim3 grid(n / 128, SPLITS);
    rbf_f16_kernel<<<grid, THREADS, SMEM_TOTAL>>>(out, nChunks, cps);
}

// round 13
// speedup vs baseline: 1.1082x; 1.1082x over previous
#include <cuda_runtime.h>
#include <cuda_fp16.h>
#include <cstdint>

#define DIM 128
#define OUTD 64
#define BC 64
#define SPLITS 18
#define THREADS 256
#define NPAD 50048              // 782 * 64, padded train rows
#define NFEAT 2048

#define TSTRIDE 136             // fp16 per row of A/T tiles
#define TROWB   (TSTRIDE * 2)   // 272 B
#define WROWB   144             // W tile row bytes (72 halfs)

#define OFF_A   0
#define SZ_A    (128 * TROWB)             // 34816
#define OFF_T   (OFF_A + SZ_A)
#define SZ_T    (BC * TROWB)              // 17408 x2
#define OFF_W   (OFF_T + 2 * SZ_T)        // 69632
#define SZ_W    (BC * WROWB)              // 9216  x2
#define OFF_T2  (OFF_W + 2 * SZ_W)        // 88064, 2 x 512B
#define SMEM_TOTAL (OFF_T2 + 1024)        // 89088  -> 2 CTAs/SM

// k = exp(-dist/(2*RBF)) = 2^(-sqrt(d2p)), d2p = B2C*(x2 + t2 - 2 dot)
#define B2C ((float)((1.4426950408889634 / (2.0 * 10.077141124806595)) * \
                     (1.4426950408889634 / (2.0 * 10.077141124806595))))
#define NEG2B2C (-2.0f * B2C)

// prep_all grid partition
#define ROWBLKS ((NPAD + NFEAT) / 8)
#define WBLKS   (NPAD * OUTD / 4 / THREADS)
#define ZBLKS   (NFEAT * OUTD / 4 / THREADS)
#define PREP_GRID (ROWBLKS + WBLKS + ZBLKS)

// ---- persistent device scratch ----
__device__ __half d_train16[NPAD * DIM];
__device__ __half d_w16[NPAD * OUTD];
__device__ __half d_feat16[NFEAT * DIM];
__device__ float  d_t2[NPAD];
__device__ float  d_x2[NFEAT];

// ---------- PTX helpers ----------
__device__ __forceinline__ uint32_t smem_u32(const void* p) {
    uint32_t a;
    asm("{ .reg .u64 t; cvta.to.shared.u64 t, %1; cvt.u32.u64 %0, t; }"
        : "=r"(a) : "l"(p));
    return a;
}
__device__ __forceinline__ void cpa16(uint32_t dst, const void* src) {
    asm volatile("cp.async.cg.shared.global [%0], [%1], 16;"
                 :: "r"(dst), "l"(src));
}
#define CP_COMMIT() asm volatile("cp.async.commit_group;" ::: "memory")
#define CP_WAIT0()  asm volatile("cp.async.wait_group 0;" ::: "memory")

__device__ __forceinline__ void ldsm4(uint32_t* r, uint32_t addr) {
    asm volatile("ldmatrix.sync.aligned.m8n8.x4.shared.b16 {%0,%1,%2,%3}, [%4];"
                 : "=r"(r[0]), "=r"(r[1]), "=r"(r[2]), "=r"(r[3]) : "r"(addr));
}
__device__ __forceinline__ void ldsm4t(uint32_t* r, uint32_t addr) {
    asm volatile("ldmatrix.sync.aligned.m8n8.x4.trans.shared.b16 {%0,%1,%2,%3}, [%4];"
                 : "=r"(r[0]), "=r"(r[1]), "=r"(r[2]), "=r"(r[3]) : "r"(addr));
}
__device__ __forceinline__ void mma_f16(float* c, const uint32_t* a, const uint32_t* b) {
    asm volatile("mma.sync.aligned.m16n8k16.row.col.f32.f16.f16.f32 "
                 "{%0,%1,%2,%3}, {%4,%5,%6,%7}, {%8,%9}, {%0,%1,%2,%3};"
                 : "+f"(c[0]), "+f"(c[1]), "+f"(c[2]), "+f"(c[3])
                 : "r"(a[0]), "r"(a[1]), "r"(a[2]), "r"(a[3]), "r"(b[0]), "r"(b[1]));
}
__device__ __forceinline__ float fast_sqrt(float x) {
    float r; asm("sqrt.approx.f32 %0, %1;" : "=f"(r) : "f"(x)); return r;
}
__device__ __forceinline__ float fast_ex2(float x) {
    float r; asm("ex2.approx.f32 %0, %1;" : "=f"(r) : "f"(x)); return r;
}
__device__ __forceinline__ uint32_t pack_h2(float a, float b) {
    __half2 p = __floats2half2_rn(a, b);
    return *(uint32_t*)&p;
}

// ---------- fused prep kernel ----------
__global__ void prep_all(const float* __restrict__ feat,
                         const float* __restrict__ train,
                         const float* __restrict__ w,
                         float* __restrict__ out, int N, int n) {
    int b = blockIdx.x;
    if (b < ROWBLKS) {
        int r = b * 8 + (threadIdx.x >> 5);
        int lid = threadIdx.x & 31;
        const float* src; __half* dst; float* nrm; int nValid, row;
        if (r < NPAD) { src = train; dst = d_train16; nrm = d_t2; nValid = N;  row = r; }
        else          { src = feat;  dst = d_feat16;  nrm = d_x2; nValid = n; row = r - NPAD; }
        float4 v = make_float4(0.f, 0.f, 0.f, 0.f);
        if (row < nValid) v = *(const float4*)(src + (size_t)row * DIM + lid * 4);
        uint32_t p0 = pack_h2(v.x, v.y), p1 = pack_h2(v.z, v.w);
        *(uint2*)(dst + (size_t)row * DIM + lid * 4) = make_uint2(p0, p1);
        float2 f0 = __half22float2(*(__half2*)&p0);
        float2 f1 = __half22float2(*(__half2*)&p1);
        float s = f0.x * f0.x + f0.y * f0.y + f1.x * f1.x + f1.y * f1.y;
        #pragma unroll
        for (int o = 16; o > 0; o >>= 1) s += __shfl_xor_sync(0xffffffffu, s, o);
        if (lid == 0) nrm[row] = s * B2C;
    } else if (b < ROWBLKS + WBLKS) {
        int idx = (b - ROWBLKS) * THREADS + threadIdx.x;
        int r = idx >> 4, c4 = idx & 15;
        float4 v = make_float4(0.f, 0.f, 0.f, 0.f);
        if (r < N) v = *(const float4*)(w + (size_t)r * OUTD + c4 * 4);
        *(uint2*)(d_w16 + (size_t)r * OUTD + c4 * 4) =
            make_uint2(pack_h2(v.x, v.y), pack_h2(v.z, v.w));
    } else {
        int idx = (b - ROWBLKS - WBLKS) * THREADS + threadIdx.x;
        ((float4*)out)[idx] = make_float4(0.f, 0.f, 0.f, 0.f);
    }
}

// ---------- main fused kernel ----------
__global__ void __launch_bounds__(THREADS, 2)
rbf_f16_kernel(float* __restrict__ out, int nChunks, int cps)
{
    extern __shared__ uint8_t sm[];
    uint32_t smb = smem_u32(sm);

    const int t = threadIdx.x, wid = t >> 5, lid = t & 31;
    const int qr = lid >> 2, qc = lid & 3;
    const int mb = wid;              // row band of 16

    const int rowBase = blockIdx.x * 128;
    const int chunk0  = blockIdx.y * cps;
    const int nc      = min(chunk0 + cps, nChunks) - chunk0;

    const int tr = t >> 4, tc16 = t & 15;
    const int wr = t >> 3, wc8 = t & 7;

    // ---- prologue: A + chunk0 tiles in one group ----
    #pragma unroll
    for (int i = 0; i < 8; i++)
        cpa16(smb + OFF_A + (uint32_t)(tr + i * 16) * TROWB + tc16 * 16,
              d_feat16 + (size_t)(rowBase + tr + i * 16) * DIM + tc16 * 8);
    {
        const int c0 = chunk0 * BC;
        #pragma unroll
        for (int i = 0; i < 4; i++)
            cpa16(smb + OFF_T + (uint32_t)(tr + i * 16) * TROWB + tc16 * 16,
                  d_train16 + (size_t)(c0 + tr + i * 16) * DIM + tc16 * 8);
        #pragma unroll
        for (int i = 0; i < 2; i++)
            cpa16(smb + OFF_W + (uint32_t)(wr + i * 32) * WROWB + wc8 * 16,
                  d_w16 + (size_t)(c0 + wr + i * 32) * OUTD + wc8 * 8);
        if (t < 16) cpa16(smb + OFF_T2 + t * 16, d_t2 + c0 + t * 4);
    }
    CP_COMMIT();

    const float x2lo = d_x2[rowBase + mb * 16 + qr];
    const float x2hi = d_x2[rowBase + mb * 16 + qr + 8];

    const int aRowL    = lid & 15;
    const int aColHalf = (lid >> 4) << 3;
    const int bRowOff  = ((lid >> 4) << 3) + (lid & 7);
    const int bColOff  = lid & 8;
    const int wKrow    = (((lid >> 3) & 1) << 3) + (lid & 7);
    const int wNcol    = (lid >> 4) << 3;

    float c2[8][4];
    #pragma unroll
    for (int nt = 0; nt < 8; nt++)
        #pragma unroll
        for (int q = 0; q < 4; q++) c2[nt][q] = 0.f;

    CP_WAIT0();
    __syncthreads();

    // ---- hoist A fragments for the whole kernel (A tile is invariant) ----
    uint32_t afr[8][4];
    #pragma unroll
    for (int ks = 0; ks < 8; ks++)
        ldsm4(afr[ks], smb + OFF_A
              + (uint32_t)(mb * 16 + aRowL) * TROWB
              + (uint32_t)(ks * 16 + aColHalf) * 2);

    for (int i = 0; i < nc; i++) {
        const int cur = i & 1, nxt = cur ^ 1;
        const uint32_t sTb = smb + OFF_T + cur * SZ_T;
        const uint32_t sWb = smb + OFF_W + cur * SZ_W;
        const float* sT2c = (const float*)(sm + OFF_T2 + cur * 512);

        // ---- prefetch chunk i+1 into [nxt] ----
        if (i + 1 < nc) {
            const int c0 = (chunk0 + i + 1) * BC;
            #pragma unroll
            for (int j = 0; j < 4; j++)
                cpa16(smb + OFF_T + nxt * SZ_T
                          + (uint32_t)(tr + j * 16) * TROWB + tc16 * 16,
                      d_train16 + (size_t)(c0 + tr + j * 16) * DIM + tc16 * 8);
            #pragma unroll
            for (int j = 0; j < 2; j++)
                cpa16(smb + OFF_W + nxt * SZ_W
                          + (uint32_t)(wr + j * 32) * WROWB + wc8 * 16,
                      d_w16 + (size_t)(c0 + wr + j * 32) * OUTD + wc8 * 8);
            if (t < 16) cpa16(smb + OFF_T2 + nxt * 512 + t * 16, d_t2 + c0 + t * 4);
        }
        CP_COMMIT();

        // ---- per-16-col slice: GEMM1 -> epilogue -> GEMM2 (slices independent)
        #pragma unroll
        for (int s = 0; s < 4; s++) {
            // GEMM1 slice: rows mb*16.., chunk cols s*16..s*16+15
            float c1s[2][4];
            #pragma unroll
            for (int h = 0; h < 2; h++)
                #pragma unroll
                for (int q = 0; q < 4; q++) c1s[h][q] = 0.f;

            #pragma unroll
            for (int ks = 0; ks < 8; ks++) {
                uint32_t rr[4];
                ldsm4(rr, sTb
                      + (uint32_t)(s * 16 + bRowOff) * TROWB
                      + (uint32_t)(ks * 16 + bColOff) * 2);
                mma_f16(c1s[0], afr[ks], &rr[0]);
                mma_f16(c1s[1], afr[ks], &rr[2]);
            }

            // epilogue slice
            const int cb = s * 16;
            float2 t2a = *(float2*)&sT2c[cb + 2 * qc];
            float2 t2b = *(float2*)&sT2c[cb + 8 + 2 * qc];
            float kk[2][4];
            #pragma unroll
            for (int half = 0; half < 2; half++) {
                const float* cc = c1s[half];
                float2 t2p = half ? t2b : t2a;
                #pragma unroll
                for (int q = 0; q < 4; q++) {
                    float x2q = (q >> 1) ? x2hi : x2lo;
                    float tq  = (q & 1) ? t2p.y : t2p.x;
                    float d2  = fmaxf(fmaf(NEG2B2C, cc[q], x2q + tq), 0.f);
                    kk[half][q] = fast_ex2(-fast_sqrt(d2));
                }
            }
            uint32_t ah[4];
            #pragma unroll
            for (int r = 0; r < 4; r++)
                ah[r] = pack_h2(kk[r >> 1][(r & 1) * 2],
                                kk[r >> 1][(r & 1) * 2 + 1]);

            // GEMM2 slice: k = chunk cols s*16..s*16+15
            const uint32_t wrow = (uint32_t)(cb + wKrow) * WROWB;
            #pragma unroll
            for (int u = 0; u < 4; u++) {
                uint32_t bh[4];
                ldsm4t(bh, sWb + wrow + (uint32_t)(u * 16 + wNcol) * 2);
                mma_f16(c2[2 * u],     ah, &bh[0]);
                mma_f16(c2[2 * u + 1], ah, &bh[2]);
            }
        }

        CP_WAIT0();
        __syncthreads();
    }

    // ---- accumulate into global out ----
    #pragma unroll
    for (int nt = 0; nt < 8; nt++) {
        int c = nt * 8 + 2 * qc;
        #pragma unroll
        for (int q = 0; q < 4; q++) {
            int r = rowBase + mb * 16 + qr + ((q >> 1) << 3);
            atomicAdd(out + (size_t)r * OUTD + c + (q & 1), c2[nt][q]);
        }
    }
}

extern "C" void kernel_launch(void* const* d_in, const int* in_sizes, int n_in,
                              void* d_out, int out_size) {
    const float* features = (const float*)d_in[0];
    const float* train    = (const float*)d_in[1];
    const float* weights  = (const float*)d_in[2];
    float* out = (float*)d_out;

    int n = in_sizes[0] / DIM;    // 2048
    int N = in_sizes[1] / DIM;    // 50000

    int nChunks = (N + BC - 1) / BC;                 // 782
    int cps     = (nChunks + SPLITS - 1) / SPLITS;   // 44

    cudaFuncSetAttribute(rbf_f16_kernel,
                         cudaFuncAttributeMaxDynamicSharedMemorySize, SMEM_TOTAL);

    prep_all<<<PREP_GRID, THREADS>>>(features, train, weights, out, N, n);

    dim3 grid(n / 128, SPLITS);
    rbf_f16_kernel<<<grid, THREADS, SMEM_TOTAL>>>(out, nChunks, cps);
}